// round 12
// baseline (speedup 1.0000x reference)
#include <cuda_runtime.h>
#include <cuda_fp16.h>

#define NN 10000
#define NE 320000
#define FULLM 0xffffffffu

// ---------------- scratch ----------------
__device__ __align__(16) float g_q[NN * 64];
__device__ __align__(16) __half2 g_vh[NN * 288];   // v_nodes as half2 (288 pairs = 576 cols)
__device__ __align__(16) float g_wexp[NE * 8];
__device__ __align__(16) float g_agg[NN * 576];
__device__ __align__(16) float g_p[NN * 64];
__device__ float g_maskf[NN];
__device__ int g_deg[NN];
__device__ int g_cur[NN];
__device__ int g_off[NN + 1];
__device__ int g_srcp[NE];

// ---------------- helpers ----------------
static __device__ __forceinline__ unsigned long long pack2(float x, float y) {
    unsigned long long r; asm("mov.b64 %0, {%1,%2};" : "=l"(r) : "f"(x), "f"(y)); return r;
}
static __device__ __forceinline__ unsigned long long dup2(float x) {
    unsigned long long r; asm("mov.b64 %0, {%1,%1};" : "=l"(r) : "f"(x)); return r;
}
static __device__ __forceinline__ void unpack2(unsigned long long v, float& x, float& y) {
    asm("mov.b64 {%0,%1}, %2;" : "=f"(x), "=f"(y) : "l"(v));
}
static __device__ __forceinline__ void ffma2(unsigned long long& d, unsigned long long a, unsigned long long b) {
    asm("fma.rn.f32x2 %0, %1, %2, %0;" : "+l"(d) : "l"(a), "l"(b));
}
static __device__ __forceinline__ float silu_f(float x) { return x / (1.f + __expf(-x)); }
static __device__ __forceinline__ unsigned long long h2f2(unsigned h) {
    float2 f = __half22float2(*(__half2*)&h);
    return pack2(f.x, f.y);
}
static __device__ __forceinline__ void mma16816(
    float& c0, float& c1, float& c2, float& c3,
    unsigned a0, unsigned a1, unsigned a2, unsigned a3,
    unsigned b0, unsigned b1) {
    asm volatile(
        "mma.sync.aligned.m16n8k16.row.col.f32.f16.f16.f32 "
        "{%0,%1,%2,%3}, {%4,%5,%6,%7}, {%8,%9}, {%0,%1,%2,%3};"
        : "+f"(c0), "+f"(c1), "+f"(c2), "+f"(c3)
        : "r"(a0), "r"(a1), "r"(a2), "r"(a3), "r"(b0), "r"(b1));
}

// ---------------- mask conv (block 0) + degree count ----------------
__global__ void k_mask_count(const void* __restrict__ p, const int* __restrict__ ei) {
    int e = blockIdx.x * 256 + threadIdx.x;
    atomicAdd(&g_deg[ei[NE + e]], 1);
    if (blockIdx.x == 0) {
        const unsigned* u = (const unsigned*)p;
        __shared__ int okf, oki;
        if (threadIdx.x == 0) { okf = 1; oki = 1; }
        __syncthreads();
        for (int i = threadIdx.x; i < 2500; i += 256) {
            unsigned v = u[i];
            if (!(v == 0u || v == 0x3F800000u)) okf = 0;
            if (!(v == 0u || v == 1u)) oki = 0;
        }
        __syncthreads();
        int t = okf ? 0 : (oki ? 1 : 2);
        for (int i = threadIdx.x; i < NN; i += 256) {
            float m;
            if (t == 0) m = ((const float*)p)[i];
            else if (t == 1) m = (float)(((const int*)p)[i] != 0);
            else m = ((const unsigned char*)p)[i] ? 1.f : 0.f;
            g_maskf[i] = m;
        }
    }
}

// ---------------- scan; resets g_deg/g_cur ----------------
__global__ void k_scan() {
    __shared__ int wsum[32];
    __shared__ int carry;
    int tid = threadIdx.x, lane = tid & 31, wid = tid >> 5;
    if (tid == 0) carry = 0;
    __syncthreads();
    for (int base = 0; base < NN; base += 1024) {
        int i = base + tid;
        int v = (i < NN) ? g_deg[i] : 0;
        int x = v;
#pragma unroll
        for (int s = 1; s < 32; s <<= 1) { int t = __shfl_up_sync(FULLM, x, s); if (lane >= s) x += t; }
        if (lane == 31) wsum[wid] = x;
        __syncthreads();
        if (wid == 0) {
            int y = wsum[lane];
#pragma unroll
            for (int s = 1; s < 32; s <<= 1) { int t = __shfl_up_sync(FULLM, y, s); if (lane >= s) y += t; }
            wsum[lane] = y;
        }
        __syncthreads();
        int prefix = carry + (wid ? wsum[wid - 1] : 0);
        if (i < NN) { g_off[i] = prefix + x - v; g_deg[i] = 0; g_cur[i] = 0; }
        __syncthreads();
        if (tid == 0) carry += wsum[31];
        __syncthreads();
    }
    if (tid == 0) g_off[NN] = NE;
}

// ---------------- node prep: q halves + v -> half2 ----------------
__global__ __launch_bounds__(256) void k_node_prep(
    const float* __restrict__ bb_emb, const float* __restrict__ bb_rel,
    const float* __restrict__ Wa1, const float* __restrict__ Wv) {
    __shared__ __align__(16) unsigned long long sWvP[35 * 32];
    __shared__ __align__(16) unsigned long long sWaP[35 * 32];
    int tid = threadIdx.x;
    for (int i = tid; i < 35 * 32; i += 256) {
        int k = i >> 5, j = i & 31;
        ((float2*)sWvP)[i] = make_float2(Wv[k * 64 + 2 * j], Wv[k * 64 + 2 * j + 1]);
        ((float2*)sWaP)[i] = make_float2(Wa1[k * 32 + j], Wa1[(k + 35) * 32 + j]);
    }
    __syncthreads();
    int lane = tid & 31;
    int n = blockIdx.x * 8 + (tid >> 5);
    float mk = g_maskf[n];

    float r0 = bb_emb[n * 288 + lane];
    unsigned long long accq = 0ull;
#pragma unroll
    for (int k = 0; k < 32; k++)
        ffma2(accq, dup2(__shfl_sync(FULLM, r0, k)), sWaP[k * 32 + lane]);
    ffma2(accq, dup2(mk), sWaP[34 * 32 + lane]);
    float qs, qd; unpack2(accq, qs, qd);
    g_q[n * 64 + lane] = qs;
    g_q[n * 64 + 32 + lane] = qd;

#pragma unroll
    for (int c = 0; c < 9; c++) {
        float f = bb_emb[n * 288 + c * 32 + lane];
        unsigned long long acc = 0ull;
        if (c == 0) {
            ffma2(acc, dup2(mk), sWvP[34 * 32 + lane]);
        } else if (c <= 3) {
#pragma unroll
            for (int b = 0; b < 3; b++)
                ffma2(acc, dup2(bb_rel[n * 9 + b * 3 + (c - 1)]), sWvP[(32 + b) * 32 + lane]);
        }
#pragma unroll
        for (int k = 0; k < 32; k++)
            ffma2(acc, dup2(__shfl_sync(FULLM, f, k)), sWvP[k * 32 + lane]);
        float a0, a1; unpack2(acc, a0, a1);
        g_vh[n * 288 + c * 32 + lane] = __floats2half2_rn(a0, a1);
    }
}

// ---------------- edge logits: register-tiled FFMA2 GEMM (unchanged) ----------------
__global__ __launch_bounds__(256, 3) void k_logits(
    const float* __restrict__ ef, const int* __restrict__ ei,
    const float* __restrict__ Wa1, const float* __restrict__ Wa2) {
    __shared__ __align__(16) float s_buf[9216];
    __shared__ __align__(16) float s_w[2048];
    __shared__ __align__(16) float s_w2r[4 * 264];
    __shared__ int s_si[256], s_di[256];
    int tid = threadIdx.x;
    int e0 = blockIdx.x * 256;
    for (int i = tid; i < 2048; i += 256) s_w[i] = Wa1[2240 + i];
    for (int i = tid; i < 1024; i += 256) s_w2r[(i >> 8) * 264 + (i & 255)] = Wa2[i & 255];
    s_si[tid] = ei[e0 + tid]; s_di[tid] = ei[NE + e0 + tid];
    __syncthreads();

    float4* qv4 = (float4*)s_buf;
    for (int i = tid; i < 2048; i += 256) {
        int r = i >> 3, slot = i & 7;
        float4 a = ((const float4*)(g_q + s_si[r] * 64))[slot];
        float4 b = ((const float4*)(g_q + s_di[r] * 64 + 32))[slot];
        qv4[r * 9 + slot] = make_float4(a.x + b.x, a.y + b.y, a.z + b.z, a.w + b.w);
    }
    __syncthreads();

    int lane = tid & 31, w = tid >> 5;
    int eg = lane & 7, og = lane >> 3;
    int Eb = w * 32 + eg * 4;
    int gb = Eb >> 2;
    unsigned long long acc[16];
#pragma unroll
    for (int e = 0; e < 4; e++) {
        float4 fa = qv4[(Eb + e) * 9 + og * 2];
        float4 fb = qv4[(Eb + e) * 9 + og * 2 + 1];
        acc[e * 4 + 0] = pack2(fa.x, fa.y);
        acc[e * 4 + 1] = pack2(fa.z, fa.w);
        acc[e * 4 + 2] = pack2(fb.x, fb.y);
        acc[e * 4 + 3] = pack2(fb.z, fb.w);
    }

#pragma unroll
    for (int ph = 0; ph < 2; ph++) {
        __syncthreads();
        for (int i = tid; i < 2048; i += 256) {
            int r = i >> 3, c4 = i & 7;
            float4 v = *(const float4*)(ef + (size_t)(e0 + r) * 64 + ph * 32 + c4 * 4);
            int g = r >> 2, rl = r & 3;
            int gs = (g & 56) | ((g ^ c4) & 7);
            float* dp = s_buf + gs * 4 + rl;
            dp[(c4 * 4 + 0) * 260] = v.x;
            dp[(c4 * 4 + 1) * 260] = v.y;
            dp[(c4 * 4 + 2) * 260] = v.z;
            dp[(c4 * 4 + 3) * 260] = v.w;
        }
        __syncthreads();
        const float* wbase = s_w + ph * 1024 + og * 8;
#pragma unroll 4
        for (int k = 0; k < 32; k++) {
            int gs = (gb & 56) | ((gb ^ (k >> 2)) & 7);
            float4 a4 = *(const float4*)(s_buf + k * 260 + gs * 4);
            ulonglong2 u0 = *(const ulonglong2*)(wbase + k * 32);
            ulonglong2 u1 = *(const ulonglong2*)(wbase + k * 32 + 4);
            unsigned long long ax;
            ax = dup2(a4.x);
            ffma2(acc[0], ax, u0.x); ffma2(acc[1], ax, u0.y); ffma2(acc[2], ax, u1.x); ffma2(acc[3], ax, u1.y);
            ax = dup2(a4.y);
            ffma2(acc[4], ax, u0.x); ffma2(acc[5], ax, u0.y); ffma2(acc[6], ax, u1.x); ffma2(acc[7], ax, u1.y);
            ax = dup2(a4.z);
            ffma2(acc[8], ax, u0.x); ffma2(acc[9], ax, u0.y); ffma2(acc[10], ax, u1.x); ffma2(acc[11], ax, u1.y);
            ax = dup2(a4.w);
            ffma2(acc[12], ax, u0.x); ffma2(acc[13], ax, u0.y); ffma2(acc[14], ax, u1.x); ffma2(acc[15], ax, u1.y);
        }
    }

    const float* w2b = s_w2r + og * 264;
#pragma unroll
    for (int e = 0; e < 4; e++) {
        int r = Eb + e;
        float pl[8] = {0, 0, 0, 0, 0, 0, 0, 0};
#pragma unroll
        for (int p = 0; p < 4; p++) {
            float x0, x1; unpack2(acc[e * 4 + p], x0, x1);
            float s0 = silu_f(x0), s1 = silu_f(x1);
            const float4* wr = (const float4*)(w2b + (og * 8 + 2 * p) * 8);
            float4 wa = wr[0], wb = wr[1], wc = wr[2], wd = wr[3];
            pl[0] += s0 * wa.x + s1 * wc.x; pl[1] += s0 * wa.y + s1 * wc.y;
            pl[2] += s0 * wa.z + s1 * wc.z; pl[3] += s0 * wa.w + s1 * wc.w;
            pl[4] += s0 * wb.x + s1 * wd.x; pl[5] += s0 * wb.y + s1 * wd.y;
            pl[6] += s0 * wb.z + s1 * wd.z; pl[7] += s0 * wb.w + s1 * wd.w;
        }
#pragma unroll
        for (int h = 0; h < 8; h++) {
            pl[h] += __shfl_xor_sync(FULLM, pl[h], 8);
            pl[h] += __shfl_xor_sync(FULLM, pl[h], 16);
        }
        if (og == 0) {
            int d = s_di[r];
            int pos = g_off[d] + atomicAdd(&g_cur[d], 1);
            g_srcp[pos] = s_si[r];
            float4* lo = (float4*)(g_wexp + (size_t)pos * 8);
            lo[0] = make_float4(__expf(pl[0]), __expf(pl[1]), __expf(pl[2]), __expf(pl[3]));
            lo[1] = make_float4(__expf(pl[4]), __expf(pl[5]), __expf(pl[6]), __expf(pl[7]));
        }
    }
}

// ---------------- single-pass softmax aggregation over fp16 v ----------------
__global__ __launch_bounds__(256) void k_agg() {
    int lane = threadIdx.x & 31, wid = threadIdx.x >> 5;
    int n = blockIdx.x * 8 + wid;
    int st = g_off[n], en = g_off[n + 1];
    int hl = lane & 7;
    float z = 0.f;
    unsigned long long A[4] = {0, 0, 0, 0}, B[4] = {0, 0, 0, 0}, C[4] = {0, 0, 0, 0};
    if (st < en) {
        int s_nxt = __ldg(&g_srcp[st]);
        float w_nxt = __ldg(&g_wexp[(size_t)st * 8 + hl]);
        for (int i = st; i < en; i++) {
            int s = s_nxt;
            float w = w_nxt;
            if (i + 1 < en) {
                s_nxt = __ldg(&g_srcp[i + 1]);
                w_nxt = __ldg(&g_wexp[(size_t)(i + 1) * 8 + hl]);
            }
            z += w;
            unsigned long long w2 = dup2(w);
            const uint4* vb = (const uint4*)(g_vh + (size_t)s * 288);
            uint4 u;
            u = vb[lane];
            ffma2(A[0], w2, h2f2(u.x)); ffma2(A[1], w2, h2f2(u.y));
            ffma2(A[2], w2, h2f2(u.z)); ffma2(A[3], w2, h2f2(u.w));
            u = vb[32 + lane];
            ffma2(B[0], w2, h2f2(u.x)); ffma2(B[1], w2, h2f2(u.y));
            ffma2(B[2], w2, h2f2(u.z)); ffma2(B[3], w2, h2f2(u.w));
            if (lane < 8) {
                u = vb[64 + lane];
                ffma2(C[0], w2, h2f2(u.x)); ffma2(C[1], w2, h2f2(u.y));
                ffma2(C[2], w2, h2f2(u.z)); ffma2(C[3], w2, h2f2(u.w));
            }
        }
    }
    float rz = 1.f / (z + 1e-9f);
    float4* ag4 = (float4*)(g_agg + n * 576);
    float x0, x1, x2, x3;
    unpack2(A[0], x0, x1); unpack2(A[1], x2, x3);
    ag4[2 * lane] = make_float4(x0 * rz, x1 * rz, x2 * rz, x3 * rz);
    unpack2(A[2], x0, x1); unpack2(A[3], x2, x3);
    ag4[2 * lane + 1] = make_float4(x0 * rz, x1 * rz, x2 * rz, x3 * rz);
    unpack2(B[0], x0, x1); unpack2(B[1], x2, x3);
    ag4[2 * lane + 64] = make_float4(x0 * rz, x1 * rz, x2 * rz, x3 * rz);
    unpack2(B[2], x0, x1); unpack2(B[3], x2, x3);
    ag4[2 * lane + 65] = make_float4(x0 * rz, x1 * rz, x2 * rz, x3 * rz);
    if (lane < 8) {
        unpack2(C[0], x0, x1); unpack2(C[1], x2, x3);
        ag4[2 * lane + 128] = make_float4(x0 * rz, x1 * rz, x2 * rz, x3 * rz);
        unpack2(C[2], x0, x1); unpack2(C[3], x2, x3);
        ag4[2 * lane + 129] = make_float4(x0 * rz, x1 * rz, x2 * rz, x3 * rz);
    }
}

// ---------------- node output MLP + p precompute ----------------
__global__ __launch_bounds__(256) void k_node_out(
    const float* __restrict__ Wo, const float* __restrict__ W1,
    const float* __restrict__ W2, const float* __restrict__ We1,
    float* __restrict__ out_node) {
    __shared__ __align__(16) float2 sWoP[32 * 32];
    __shared__ float sW1[1024], sW2[1024], sWe[2048];
    __shared__ __align__(16) float sAgg[8 * 576];
    int tid = threadIdx.x;
    for (int i = tid; i < 1024; i += 256) {
        int jp = i >> 5, l = i & 31;
        sWoP[i] = make_float2(Wo[(2 * jp) * 32 + l], Wo[(2 * jp + 1) * 32 + l]);
        sW1[i] = W1[i]; sW2[i] = W2[i];
    }
    for (int i = tid; i < 2048; i += 256) sWe[i] = We1[i];
    {
        const float4* src = (const float4*)(g_agg + (size_t)blockIdx.x * 8 * 576);
        float4* dst = (float4*)sAgg;
        for (int i = tid; i < 8 * 144; i += 256) dst[i] = src[i];
    }
    __syncthreads();
    int lane = tid & 31, wid = tid >> 5;
    int n = blockIdx.x * 8 + wid;
    const float* sa = sAgg + wid * 576;

    float ao[9];
#pragma unroll
    for (int c = 0; c < 9; c++) {
        unsigned long long acc2 = 0ull;
        const unsigned long long* sav = (const unsigned long long*)(sa + c * 64);
#pragma unroll
        for (int jp = 0; jp < 32; jp++)
            ffma2(acc2, sav[jp], *(const unsigned long long*)&sWoP[jp * 32 + lane]);
        float x0, x1; unpack2(acc2, x0, x1);
        ao[c] = x0 + x1;
    }
    float hr[9];
#pragma unroll
    for (int c = 0; c < 9; c++) {
        float acc = 0.f;
#pragma unroll
        for (int o = 0; o < 32; o++) acc += __shfl_sync(FULLM, ao[c], o) * sW1[o * 32 + lane];
        hr[c] = acc;
    }
    float gate = silu_f(hr[0]);
    float nn0 = 0.f;
#pragma unroll
    for (int c = 0; c < 9; c++) {
        float t = hr[c] * gate;
        float acc = ao[c];
#pragma unroll
        for (int o = 0; o < 32; o++) acc += __shfl_sync(FULLM, t, o) * sW2[o * 32 + lane];
        out_node[n * 288 + c * 32 + lane] = acc;
        if (c == 0) nn0 = acc;
    }
    float ps = 0.f, pd = 0.f;
#pragma unroll
    for (int k = 0; k < 32; k++) {
        float u = __shfl_sync(FULLM, nn0, k);
        ps += u * sWe[k * 32 + lane];
        pd += u * sWe[(32 + k) * 32 + lane];
    }
    g_p[n * 64 + lane] = ps;
    g_p[n * 64 + 32 + lane] = pd;
}

// ---------------- edge output MLP: HMMA tensor-core GEMMs ----------------
// warp = [32 edges x 32 outs]; A=ef fp16 stride-72 (conflict-free direct frags),
// B transposed fp16; GEMM1 C-init = fp32 psum; silu->fp16 stride-40 -> GEMM2.
__global__ __launch_bounds__(256) void k_edge_out(
    const float* __restrict__ ef, const int* __restrict__ ei,
    const float* __restrict__ We1, const float* __restrict__ We2,
    float* __restrict__ out_edge) {
    extern __shared__ char dsm[];
    float* s_ps = (float*)dsm;                       // [256][36] fp32 psum
    __half* s_efh = (__half*)(dsm + 36864);          // [256][72]
    __half* s_sv  = (__half*)(dsm + 73728);          // [256][40]
    __half* s_w1t = (__half*)(dsm + 94208);          // [32][72]  We1T
    __half* s_w2t = (__half*)(dsm + 98816);          // [64][40]  We2T
    int* s_si = (int*)(dsm + 103936);
    int* s_di = (int*)(dsm + 104960);
    int tid = threadIdx.x;
    int e0 = blockIdx.x * 256;

    for (int i = tid; i < 2048; i += 256) {
        int k = i >> 5, n = i & 31;
        s_w1t[n * 72 + k] = __float2half_rn(We1[2048 + i]);
    }
    for (int i = tid; i < 2048; i += 256) {
        int k = i >> 6, n = i & 63;
        s_w2t[n * 40 + k] = __float2half_rn(We2[i]);
    }
    s_si[tid] = ei[e0 + tid]; s_di[tid] = ei[NE + e0 + tid];
    __syncthreads();

    // psum gather (fp32) + ef -> fp16 staging
    float4* qv4 = (float4*)s_ps;
    for (int i = tid; i < 2048; i += 256) {
        int r = i >> 3, slot = i & 7;
        float4 a = ((const float4*)(g_p + s_si[r] * 64))[slot];
        float4 b = ((const float4*)(g_p + s_di[r] * 64 + 32))[slot];
        qv4[r * 9 + slot] = make_float4(a.x + b.x, a.y + b.y, a.z + b.z, a.w + b.w);
    }
    for (int i = tid; i < 4096; i += 256) {
        int r = i >> 4, c4 = i & 15;
        float4 v = *(const float4*)(ef + (size_t)(e0 + r) * 64 + c4 * 4);
        __half2 h01 = __floats2half2_rn(v.x, v.y);
        __half2 h23 = __floats2half2_rn(v.z, v.w);
        uint2 u = make_uint2(*(unsigned*)&h01, *(unsigned*)&h23);
        *(uint2*)(s_efh + r * 72 + c4 * 4) = u;
    }
    __syncthreads();

    int lane = tid & 31, w = tid >> 5;
    int g = lane >> 2, tig = lane & 3;
    int mb = w * 32;

    float acc[2][4][4];
#pragma unroll
    for (int mt = 0; mt < 2; mt++)
#pragma unroll
        for (int nt = 0; nt < 4; nt++) {
            const float* pr = s_ps + (mb + mt * 16 + g) * 36 + nt * 8 + 2 * tig;
            float2 lo = *(const float2*)pr;
            float2 hi = *(const float2*)(pr + 8 * 36);
            acc[mt][nt][0] = lo.x; acc[mt][nt][1] = lo.y;
            acc[mt][nt][2] = hi.x; acc[mt][nt][3] = hi.y;
        }
#pragma unroll
    for (int ks = 0; ks < 4; ks++) {
        unsigned bf0[4], bf1[4];
#pragma unroll
        for (int nt = 0; nt < 4; nt++) {
            const __half* wp = s_w1t + (nt * 8 + g) * 72 + ks * 16 + 2 * tig;
            bf0[nt] = *(const unsigned*)wp;
            bf1[nt] = *(const unsigned*)(wp + 8);
        }
#pragma unroll
        for (int mt = 0; mt < 2; mt++) {
            const __half* ap = s_efh + (mb + mt * 16 + g) * 72 + ks * 16 + 2 * tig;
            unsigned a0 = *(const unsigned*)ap;
            unsigned a1 = *(const unsigned*)(ap + 8 * 72);
            unsigned a2 = *(const unsigned*)(ap + 8);
            unsigned a3 = *(const unsigned*)(ap + 8 * 72 + 8);
#pragma unroll
            for (int nt = 0; nt < 4; nt++)
                mma16816(acc[mt][nt][0], acc[mt][nt][1], acc[mt][nt][2], acc[mt][nt][3],
                         a0, a1, a2, a3, bf0[nt], bf1[nt]);
        }
    }

    // silu -> s_sv fp16 (warp-private rows; cross-lane reuse within warp only)
#pragma unroll
    for (int mt = 0; mt < 2; mt++)
#pragma unroll
        for (int nt = 0; nt < 4; nt++) {
            int row = mb + mt * 16 + g;
            __half2 lo = __floats2half2_rn(silu_f(acc[mt][nt][0]), silu_f(acc[mt][nt][1]));
            __half2 hi = __floats2half2_rn(silu_f(acc[mt][nt][2]), silu_f(acc[mt][nt][3]));
            *(unsigned*)(s_sv + row * 40 + nt * 8 + 2 * tig) = *(unsigned*)&lo;
            *(unsigned*)(s_sv + (row + 8) * 40 + nt * 8 + 2 * tig) = *(unsigned*)&hi;
        }
    __syncwarp();

#pragma unroll
    for (int h = 0; h < 2; h++) {
        float o[2][4][4];
#pragma unroll
        for (int mt = 0; mt < 2; mt++)
#pragma unroll
            for (int nt = 0; nt < 4; nt++)
                o[mt][nt][0] = o[mt][nt][1] = o[mt][nt][2] = o[mt][nt][3] = 0.f;
#pragma unroll
        for (int ks = 0; ks < 2; ks++) {
            unsigned bf0[4], bf1[4];
#pragma unroll
            for (int nt = 0; nt < 4; nt++) {
                const __half* wp = s_w2t + (h * 32 + nt * 8 + g) * 40 + ks * 16 + 2 * tig;
                bf0[nt] = *(const unsigned*)wp;
                bf1[nt] = *(const unsigned*)(wp + 8);
            }
#pragma unroll
            for (int mt = 0; mt < 2; mt++) {
                const __half* ap = s_sv + (mb + mt * 16 + g) * 40 + ks * 16 + 2 * tig;
                unsigned a0 = *(const unsigned*)ap;
                unsigned a1 = *(const unsigned*)(ap + 8 * 40);
                unsigned a2 = *(const unsigned*)(ap + 8);
                unsigned a3 = *(const unsigned*)(ap + 8 * 40 + 8);
#pragma unroll
                for (int nt = 0; nt < 4; nt++)
                    mma16816(o[mt][nt][0], o[mt][nt][1], o[mt][nt][2], o[mt][nt][3],
                             a0, a1, a2, a3, bf0[nt], bf1[nt]);
            }
        }
#pragma unroll
        for (int mt = 0; mt < 2; mt++)
#pragma unroll
            for (int nt = 0; nt < 4; nt++) {
                int row = mb + mt * 16 + g;
                size_t go = (size_t)(e0 + row) * 64 + h * 32 + nt * 8 + 2 * tig;
                float2 r0 = *(const float2*)(ef + go);
                *(float2*)(out_edge + go) =
                    make_float2(o[mt][nt][0] + r0.x, o[mt][nt][1] + r0.y);
                float2 r1 = *(const float2*)(ef + go + 8 * 64);
                *(float2*)(out_edge + go + 8 * 64) =
                    make_float2(o[mt][nt][2] + r1.x, o[mt][nt][3] + r1.y);
            }
    }
}

// ---------------- launch ----------------
extern "C" void kernel_launch(void* const* d_in, const int* in_sizes, int n_in,
                              void* d_out, int out_size) {
    const float* bb_emb = (const float*)d_in[0];
    const float* bb_rel = (const float*)d_in[1];
    const float* ef = (const float*)d_in[2];
    const int* ei = (const int*)d_in[3];
    const void* mask = d_in[4];
    const float* Wa1 = (const float*)d_in[5];
    const float* Wa2 = (const float*)d_in[6];
    const float* Wv = (const float*)d_in[7];
    const float* Wo = (const float*)d_in[8];
    const float* W1 = (const float*)d_in[9];
    const float* W2 = (const float*)d_in[10];
    const float* We1 = (const float*)d_in[11];
    const float* We2 = (const float*)d_in[12];
    float* out_node = (float*)d_out;
    float* out_edge = out_node + (size_t)NN * 288;

    const int SMEM_EO = 105984;
    cudaFuncSetAttribute((const void*)k_edge_out,
                         cudaFuncAttributeMaxDynamicSharedMemorySize, SMEM_EO);

    k_mask_count<<<1250, 256>>>(mask, ei);
    k_scan<<<1, 1024>>>();
    k_node_prep<<<1250, 256>>>(bb_emb, bb_rel, Wa1, Wv);
    k_logits<<<1250, 256>>>(ef, ei, Wa1, Wa2);
    k_agg<<<1250, 256>>>();
    k_node_out<<<1250, 256>>>(Wo, W1, W2, We1, out_node);
    k_edge_out<<<1250, 256, SMEM_EO>>>(ef, ei, We1, We2, out_edge);
}

// round 13
// speedup vs baseline: 1.0055x; 1.0055x over previous
#include <cuda_runtime.h>
#include <cuda_fp16.h>

#define NN 10000
#define NE 320000
#define FULLM 0xffffffffu

// ---------------- scratch ----------------
__device__ __align__(16) float g_q[NN * 64];
__device__ __align__(16) __half2 g_vh[NN * 288];   // v_nodes as half2 (288 pairs = 576 cols)
__device__ __align__(16) float g_wexp[NE * 8];
__device__ __align__(16) float g_agg[NN * 576];
__device__ __align__(16) float g_p[NN * 64];
__device__ float g_maskf[NN];
__device__ int g_deg[NN];
__device__ int g_cur[NN];
__device__ int g_off[NN + 1];
__device__ int g_srcp[NE];

// ---------------- helpers ----------------
static __device__ __forceinline__ unsigned long long pack2(float x, float y) {
    unsigned long long r; asm("mov.b64 %0, {%1,%2};" : "=l"(r) : "f"(x), "f"(y)); return r;
}
static __device__ __forceinline__ unsigned long long dup2(float x) {
    unsigned long long r; asm("mov.b64 %0, {%1,%1};" : "=l"(r) : "f"(x)); return r;
}
static __device__ __forceinline__ void unpack2(unsigned long long v, float& x, float& y) {
    asm("mov.b64 {%0,%1}, %2;" : "=f"(x), "=f"(y) : "l"(v));
}
static __device__ __forceinline__ void ffma2(unsigned long long& d, unsigned long long a, unsigned long long b) {
    asm("fma.rn.f32x2 %0, %1, %2, %0;" : "+l"(d) : "l"(a), "l"(b));
}
static __device__ __forceinline__ float silu_f(float x) { return x / (1.f + __expf(-x)); }
static __device__ __forceinline__ unsigned long long h2f2(unsigned h) {
    float2 f = __half22float2(*(__half2*)&h);
    return pack2(f.x, f.y);
}

// ---------------- mask conv (block 0) + degree count ----------------
__global__ void k_mask_count(const void* __restrict__ p, const int* __restrict__ ei) {
    int e = blockIdx.x * 256 + threadIdx.x;
    atomicAdd(&g_deg[ei[NE + e]], 1);
    if (blockIdx.x == 0) {
        const unsigned* u = (const unsigned*)p;
        __shared__ int okf, oki;
        if (threadIdx.x == 0) { okf = 1; oki = 1; }
        __syncthreads();
        for (int i = threadIdx.x; i < 2500; i += 256) {
            unsigned v = u[i];
            if (!(v == 0u || v == 0x3F800000u)) okf = 0;
            if (!(v == 0u || v == 1u)) oki = 0;
        }
        __syncthreads();
        int t = okf ? 0 : (oki ? 1 : 2);
        for (int i = threadIdx.x; i < NN; i += 256) {
            float m;
            if (t == 0) m = ((const float*)p)[i];
            else if (t == 1) m = (float)(((const int*)p)[i] != 0);
            else m = ((const unsigned char*)p)[i] ? 1.f : 0.f;
            g_maskf[i] = m;
        }
    }
}

// ---------------- scan; resets g_deg/g_cur ----------------
__global__ void k_scan() {
    __shared__ int wsum[32];
    __shared__ int carry;
    int tid = threadIdx.x, lane = tid & 31, wid = tid >> 5;
    if (tid == 0) carry = 0;
    __syncthreads();
    for (int base = 0; base < NN; base += 1024) {
        int i = base + tid;
        int v = (i < NN) ? g_deg[i] : 0;
        int x = v;
#pragma unroll
        for (int s = 1; s < 32; s <<= 1) { int t = __shfl_up_sync(FULLM, x, s); if (lane >= s) x += t; }
        if (lane == 31) wsum[wid] = x;
        __syncthreads();
        if (wid == 0) {
            int y = wsum[lane];
#pragma unroll
            for (int s = 1; s < 32; s <<= 1) { int t = __shfl_up_sync(FULLM, y, s); if (lane >= s) y += t; }
            wsum[lane] = y;
        }
        __syncthreads();
        int prefix = carry + (wid ? wsum[wid - 1] : 0);
        if (i < NN) { g_off[i] = prefix + x - v; g_deg[i] = 0; g_cur[i] = 0; }
        __syncthreads();
        if (tid == 0) carry += wsum[31];
        __syncthreads();
    }
    if (tid == 0) g_off[NN] = NE;
}

// ---------------- node prep: q halves + v -> half2 ----------------
__global__ __launch_bounds__(256) void k_node_prep(
    const float* __restrict__ bb_emb, const float* __restrict__ bb_rel,
    const float* __restrict__ Wa1, const float* __restrict__ Wv) {
    __shared__ __align__(16) unsigned long long sWvP[35 * 32];
    __shared__ __align__(16) unsigned long long sWaP[35 * 32];
    int tid = threadIdx.x;
    for (int i = tid; i < 35 * 32; i += 256) {
        int k = i >> 5, j = i & 31;
        ((float2*)sWvP)[i] = make_float2(Wv[k * 64 + 2 * j], Wv[k * 64 + 2 * j + 1]);
        ((float2*)sWaP)[i] = make_float2(Wa1[k * 32 + j], Wa1[(k + 35) * 32 + j]);
    }
    __syncthreads();
    int lane = tid & 31;
    int n = blockIdx.x * 8 + (tid >> 5);
    float mk = g_maskf[n];

    float r0 = bb_emb[n * 288 + lane];
    unsigned long long accq = 0ull;
#pragma unroll
    for (int k = 0; k < 32; k++)
        ffma2(accq, dup2(__shfl_sync(FULLM, r0, k)), sWaP[k * 32 + lane]);
    ffma2(accq, dup2(mk), sWaP[34 * 32 + lane]);
    float qs, qd; unpack2(accq, qs, qd);
    g_q[n * 64 + lane] = qs;
    g_q[n * 64 + 32 + lane] = qd;

#pragma unroll
    for (int c = 0; c < 9; c++) {
        float f = bb_emb[n * 288 + c * 32 + lane];
        unsigned long long acc = 0ull;
        if (c == 0) {
            ffma2(acc, dup2(mk), sWvP[34 * 32 + lane]);
        } else if (c <= 3) {
#pragma unroll
            for (int b = 0; b < 3; b++)
                ffma2(acc, dup2(bb_rel[n * 9 + b * 3 + (c - 1)]), sWvP[(32 + b) * 32 + lane]);
        }
#pragma unroll
        for (int k = 0; k < 32; k++)
            ffma2(acc, dup2(__shfl_sync(FULLM, f, k)), sWvP[k * 32 + lane]);
        float a0, a1; unpack2(acc, a0, a1);
        g_vh[n * 288 + c * 32 + lane] = __floats2half2_rn(a0, a1);
    }
}

// ---------------- edge logits: register-tiled GEMM, 4 blocks/SM ----------------
__global__ __launch_bounds__(256, 4) void k_logits(
    const float* __restrict__ ef, const int* __restrict__ ei,
    const float* __restrict__ Wa1, const float* __restrict__ Wa2) {
    __shared__ __align__(16) float s_buf[9216];
    __shared__ __align__(16) float s_w[2048];
    __shared__ __align__(16) float s_w2r[4 * 264];
    __shared__ int s_si[256], s_di[256];
    int tid = threadIdx.x;
    int e0 = blockIdx.x * 256;
    for (int i = tid; i < 2048; i += 256) s_w[i] = Wa1[2240 + i];
    for (int i = tid; i < 1024; i += 256) s_w2r[(i >> 8) * 264 + (i & 255)] = Wa2[i & 255];
    s_si[tid] = ei[e0 + tid]; s_di[tid] = ei[NE + e0 + tid];
    __syncthreads();

    float4* qv4 = (float4*)s_buf;
    for (int i = tid; i < 2048; i += 256) {
        int r = i >> 3, slot = i & 7;
        float4 a = ((const float4*)(g_q + s_si[r] * 64))[slot];
        float4 b = ((const float4*)(g_q + s_di[r] * 64 + 32))[slot];
        qv4[r * 9 + slot] = make_float4(a.x + b.x, a.y + b.y, a.z + b.z, a.w + b.w);
    }
    __syncthreads();

    int lane = tid & 31, w = tid >> 5;
    int eg = lane & 7, og = lane >> 3;
    int Eb = w * 32 + eg * 4;
    int gb = Eb >> 2;
    unsigned long long acc[16];
#pragma unroll
    for (int e = 0; e < 4; e++) {
        float4 fa = qv4[(Eb + e) * 9 + og * 2];
        float4 fb = qv4[(Eb + e) * 9 + og * 2 + 1];
        acc[e * 4 + 0] = pack2(fa.x, fa.y);
        acc[e * 4 + 1] = pack2(fa.z, fa.w);
        acc[e * 4 + 2] = pack2(fb.x, fb.y);
        acc[e * 4 + 3] = pack2(fb.z, fb.w);
    }

#pragma unroll
    for (int ph = 0; ph < 2; ph++) {
        __syncthreads();
        for (int i = tid; i < 2048; i += 256) {
            int r = i >> 3, c4 = i & 7;
            float4 v = *(const float4*)(ef + (size_t)(e0 + r) * 64 + ph * 32 + c4 * 4);
            int g = r >> 2, rl = r & 3;
            int gs = (g & 56) | ((g ^ c4) & 7);
            float* dp = s_buf + gs * 4 + rl;
            dp[(c4 * 4 + 0) * 260] = v.x;
            dp[(c4 * 4 + 1) * 260] = v.y;
            dp[(c4 * 4 + 2) * 260] = v.z;
            dp[(c4 * 4 + 3) * 260] = v.w;
        }
        __syncthreads();
        const float* wbase = s_w + ph * 1024 + og * 8;
#pragma unroll 4
        for (int k = 0; k < 32; k++) {
            int gs = (gb & 56) | ((gb ^ (k >> 2)) & 7);
            float4 a4 = *(const float4*)(s_buf + k * 260 + gs * 4);
            ulonglong2 u0 = *(const ulonglong2*)(wbase + k * 32);
            ulonglong2 u1 = *(const ulonglong2*)(wbase + k * 32 + 4);
            unsigned long long ax;
            ax = dup2(a4.x);
            ffma2(acc[0], ax, u0.x); ffma2(acc[1], ax, u0.y); ffma2(acc[2], ax, u1.x); ffma2(acc[3], ax, u1.y);
            ax = dup2(a4.y);
            ffma2(acc[4], ax, u0.x); ffma2(acc[5], ax, u0.y); ffma2(acc[6], ax, u1.x); ffma2(acc[7], ax, u1.y);
            ax = dup2(a4.z);
            ffma2(acc[8], ax, u0.x); ffma2(acc[9], ax, u0.y); ffma2(acc[10], ax, u1.x); ffma2(acc[11], ax, u1.y);
            ax = dup2(a4.w);
            ffma2(acc[12], ax, u0.x); ffma2(acc[13], ax, u0.y); ffma2(acc[14], ax, u1.x); ffma2(acc[15], ax, u1.y);
        }
    }

    const float* w2b = s_w2r + og * 264;
#pragma unroll
    for (int e = 0; e < 4; e++) {
        int r = Eb + e;
        float pl[8] = {0, 0, 0, 0, 0, 0, 0, 0};
#pragma unroll
        for (int p = 0; p < 4; p++) {
            float x0, x1; unpack2(acc[e * 4 + p], x0, x1);
            float s0 = silu_f(x0), s1 = silu_f(x1);
            const float4* wr = (const float4*)(w2b + (og * 8 + 2 * p) * 8);
            float4 wa = wr[0], wb = wr[1], wc = wr[2], wd = wr[3];
            pl[0] += s0 * wa.x + s1 * wc.x; pl[1] += s0 * wa.y + s1 * wc.y;
            pl[2] += s0 * wa.z + s1 * wc.z; pl[3] += s0 * wa.w + s1 * wc.w;
            pl[4] += s0 * wb.x + s1 * wd.x; pl[5] += s0 * wb.y + s1 * wd.y;
            pl[6] += s0 * wb.z + s1 * wd.z; pl[7] += s0 * wb.w + s1 * wd.w;
        }
#pragma unroll
        for (int h = 0; h < 8; h++) {
            pl[h] += __shfl_xor_sync(FULLM, pl[h], 8);
            pl[h] += __shfl_xor_sync(FULLM, pl[h], 16);
        }
        if (og == 0) {
            int d = s_di[r];
            int pos = g_off[d] + atomicAdd(&g_cur[d], 1);
            g_srcp[pos] = s_si[r];
            float4* lo = (float4*)(g_wexp + (size_t)pos * 8);
            lo[0] = make_float4(__expf(pl[0]), __expf(pl[1]), __expf(pl[2]), __expf(pl[3]));
            lo[1] = make_float4(__expf(pl[4]), __expf(pl[5]), __expf(pl[6]), __expf(pl[7]));
        }
    }
}

// ---------------- single-pass softmax aggregation over fp16 v ----------------
__global__ __launch_bounds__(256) void k_agg() {
    int lane = threadIdx.x & 31, wid = threadIdx.x >> 5;
    int n = blockIdx.x * 8 + wid;
    int st = g_off[n], en = g_off[n + 1];
    int hl = lane & 7;
    float z = 0.f;
    unsigned long long A[4] = {0, 0, 0, 0}, B[4] = {0, 0, 0, 0}, C[4] = {0, 0, 0, 0};
    if (st < en) {
        int s_nxt = __ldg(&g_srcp[st]);
        float w_nxt = __ldg(&g_wexp[(size_t)st * 8 + hl]);
        for (int i = st; i < en; i++) {
            int s = s_nxt;
            float w = w_nxt;
            if (i + 1 < en) {
                s_nxt = __ldg(&g_srcp[i + 1]);
                w_nxt = __ldg(&g_wexp[(size_t)(i + 1) * 8 + hl]);
            }
            z += w;
            unsigned long long w2 = dup2(w);
            const uint4* vb = (const uint4*)(g_vh + (size_t)s * 288);
            uint4 u;
            u = vb[lane];
            ffma2(A[0], w2, h2f2(u.x)); ffma2(A[1], w2, h2f2(u.y));
            ffma2(A[2], w2, h2f2(u.z)); ffma2(A[3], w2, h2f2(u.w));
            u = vb[32 + lane];
            ffma2(B[0], w2, h2f2(u.x)); ffma2(B[1], w2, h2f2(u.y));
            ffma2(B[2], w2, h2f2(u.z)); ffma2(B[3], w2, h2f2(u.w));
            if (lane < 8) {
                u = vb[64 + lane];
                ffma2(C[0], w2, h2f2(u.x)); ffma2(C[1], w2, h2f2(u.y));
                ffma2(C[2], w2, h2f2(u.z)); ffma2(C[3], w2, h2f2(u.w));
            }
        }
    }
    float rz = 1.f / (z + 1e-9f);
    float4* ag4 = (float4*)(g_agg + n * 576);
    float x0, x1, x2, x3;
    unpack2(A[0], x0, x1); unpack2(A[1], x2, x3);
    ag4[2 * lane] = make_float4(x0 * rz, x1 * rz, x2 * rz, x3 * rz);
    unpack2(A[2], x0, x1); unpack2(A[3], x2, x3);
    ag4[2 * lane + 1] = make_float4(x0 * rz, x1 * rz, x2 * rz, x3 * rz);
    unpack2(B[0], x0, x1); unpack2(B[1], x2, x3);
    ag4[2 * lane + 64] = make_float4(x0 * rz, x1 * rz, x2 * rz, x3 * rz);
    unpack2(B[2], x0, x1); unpack2(B[3], x2, x3);
    ag4[2 * lane + 65] = make_float4(x0 * rz, x1 * rz, x2 * rz, x3 * rz);
    if (lane < 8) {
        unpack2(C[0], x0, x1); unpack2(C[1], x2, x3);
        ag4[2 * lane + 128] = make_float4(x0 * rz, x1 * rz, x2 * rz, x3 * rz);
        unpack2(C[2], x0, x1); unpack2(C[3], x2, x3);
        ag4[2 * lane + 129] = make_float4(x0 * rz, x1 * rz, x2 * rz, x3 * rz);
    }
}

// ---------------- node output MLP + p precompute ----------------
__global__ __launch_bounds__(256) void k_node_out(
    const float* __restrict__ Wo, const float* __restrict__ W1,
    const float* __restrict__ W2, const float* __restrict__ We1,
    float* __restrict__ out_node) {
    __shared__ __align__(16) float2 sWoP[32 * 32];
    __shared__ float sW1[1024], sW2[1024], sWe[2048];
    __shared__ __align__(16) float sAgg[8 * 576];
    int tid = threadIdx.x;
    for (int i = tid; i < 1024; i += 256) {
        int jp = i >> 5, l = i & 31;
        sWoP[i] = make_float2(Wo[(2 * jp) * 32 + l], Wo[(2 * jp + 1) * 32 + l]);
        sW1[i] = W1[i]; sW2[i] = W2[i];
    }
    for (int i = tid; i < 2048; i += 256) sWe[i] = We1[i];
    {
        const float4* src = (const float4*)(g_agg + (size_t)blockIdx.x * 8 * 576);
        float4* dst = (float4*)sAgg;
        for (int i = tid; i < 8 * 144; i += 256) dst[i] = src[i];
    }
    __syncthreads();
    int lane = tid & 31, wid = tid >> 5;
    int n = blockIdx.x * 8 + wid;
    const float* sa = sAgg + wid * 576;

    float ao[9];
#pragma unroll
    for (int c = 0; c < 9; c++) {
        unsigned long long acc2 = 0ull;
        const unsigned long long* sav = (const unsigned long long*)(sa + c * 64);
#pragma unroll
        for (int jp = 0; jp < 32; jp++)
            ffma2(acc2, sav[jp], *(const unsigned long long*)&sWoP[jp * 32 + lane]);
        float x0, x1; unpack2(acc2, x0, x1);
        ao[c] = x0 + x1;
    }
    float hr[9];
#pragma unroll
    for (int c = 0; c < 9; c++) {
        float acc = 0.f;
#pragma unroll
        for (int o = 0; o < 32; o++) acc += __shfl_sync(FULLM, ao[c], o) * sW1[o * 32 + lane];
        hr[c] = acc;
    }
    float gate = silu_f(hr[0]);
    float nn0 = 0.f;
#pragma unroll
    for (int c = 0; c < 9; c++) {
        float t = hr[c] * gate;
        float acc = ao[c];
#pragma unroll
        for (int o = 0; o < 32; o++) acc += __shfl_sync(FULLM, t, o) * sW2[o * 32 + lane];
        out_node[n * 288 + c * 32 + lane] = acc;
        if (c == 0) nn0 = acc;
    }
    float ps = 0.f, pd = 0.f;
#pragma unroll
    for (int k = 0; k < 32; k++) {
        float u = __shfl_sync(FULLM, nn0, k);
        ps += u * sWe[k * 32 + lane];
        pd += u * sWe[(32 + k) * 32 + lane];
    }
    g_p[n * 64 + lane] = ps;
    g_p[n * 64 + 32 + lane] = pd;
}

// ---------------- edge output MLP: register-tiled, swizzled staging, 4 blocks/SM ----------------
__global__ __launch_bounds__(256, 4) void k_edge_out(
    const float* __restrict__ ef, const int* __restrict__ ei,
    const float* __restrict__ We1, const float* __restrict__ We2,
    float* __restrict__ out_edge) {
    __shared__ __align__(16) float s_buf[9216];
    __shared__ __align__(16) float s_w1[2048];
    __shared__ __align__(16) float s_w2[2048];
    __shared__ int s_si[256], s_di[256];
    int tid = threadIdx.x;
    int e0 = blockIdx.x * 256;
    for (int i = tid; i < 2048; i += 256) { s_w1[i] = We1[2048 + i]; s_w2[i] = We2[i]; }
    s_si[tid] = ei[e0 + tid]; s_di[tid] = ei[NE + e0 + tid];
    __syncthreads();

    float4* qv4 = (float4*)s_buf;
    for (int i = tid; i < 2048; i += 256) {
        int r = i >> 3, slot = i & 7;
        float4 a = ((const float4*)(g_p + s_si[r] * 64))[slot];
        float4 b = ((const float4*)(g_p + s_di[r] * 64 + 32))[slot];
        qv4[r * 9 + slot] = make_float4(a.x + b.x, a.y + b.y, a.z + b.z, a.w + b.w);
    }
    __syncthreads();

    int lane = tid & 31, w = tid >> 5;
    int eg = lane & 7, og = lane >> 3;
    int Eb = w * 32 + eg * 4;
    int gb = Eb >> 2;
    unsigned long long acc[16];
#pragma unroll
    for (int e = 0; e < 4; e++) {
        float4 fa = qv4[(Eb + e) * 9 + og * 2];
        float4 fb = qv4[(Eb + e) * 9 + og * 2 + 1];
        acc[e * 4 + 0] = pack2(fa.x, fa.y);
        acc[e * 4 + 1] = pack2(fa.z, fa.w);
        acc[e * 4 + 2] = pack2(fb.x, fb.y);
        acc[e * 4 + 3] = pack2(fb.z, fb.w);
    }

#pragma unroll
    for (int ph = 0; ph < 2; ph++) {
        __syncthreads();
        for (int i = tid; i < 2048; i += 256) {
            int r = i >> 3, c4 = i & 7;
            float4 v = *(const float4*)(ef + (size_t)(e0 + r) * 64 + ph * 32 + c4 * 4);
            int g = r >> 2, rl = r & 3;
            int gs = (g & 56) | ((g ^ c4) & 7);
            float* dp = s_buf + gs * 4 + rl;
            dp[(c4 * 4 + 0) * 260] = v.x;
            dp[(c4 * 4 + 1) * 260] = v.y;
            dp[(c4 * 4 + 2) * 260] = v.z;
            dp[(c4 * 4 + 3) * 260] = v.w;
        }
        __syncthreads();
        const float* wbase = s_w1 + ph * 1024 + og * 8;
#pragma unroll 4
        for (int k = 0; k < 32; k++) {
            int gs = (gb & 56) | ((gb ^ (k >> 2)) & 7);
            float4 a4 = *(const float4*)(s_buf + k * 260 + gs * 4);
            ulonglong2 u0 = *(const ulonglong2*)(wbase + k * 32);
            ulonglong2 u1 = *(const ulonglong2*)(wbase + k * 32 + 4);
            unsigned long long ax;
            ax = dup2(a4.x);
            ffma2(acc[0], ax, u0.x); ffma2(acc[1], ax, u0.y); ffma2(acc[2], ax, u1.x); ffma2(acc[3], ax, u1.y);
            ax = dup2(a4.y);
            ffma2(acc[4], ax, u0.x); ffma2(acc[5], ax, u0.y); ffma2(acc[6], ax, u1.x); ffma2(acc[7], ax, u1.y);
            ax = dup2(a4.z);
            ffma2(acc[8], ax, u0.x); ffma2(acc[9], ax, u0.y); ffma2(acc[10], ax, u1.x); ffma2(acc[11], ax, u1.y);
            ax = dup2(a4.w);
            ffma2(acc[12], ax, u0.x); ffma2(acc[13], ax, u0.y); ffma2(acc[14], ax, u1.x); ffma2(acc[15], ax, u1.y);
        }
    }

    __syncthreads();
#pragma unroll
    for (int p = 0; p < 4; p++) {
        float a0x, a0y, a1x, a1y, a2x, a2y, a3x, a3y;
        unpack2(acc[0 * 4 + p], a0x, a0y);
        unpack2(acc[1 * 4 + p], a1x, a1y);
        unpack2(acc[2 * 4 + p], a2x, a2y);
        unpack2(acc[3 * 4 + p], a3x, a3y);
        int j = og * 8 + 2 * p;
        *(float4*)(s_buf + j * 260 + Eb) =
            make_float4(silu_f(a0x), silu_f(a1x), silu_f(a2x), silu_f(a3x));
        *(float4*)(s_buf + (j + 1) * 260 + Eb) =
            make_float4(silu_f(a0y), silu_f(a1y), silu_f(a2y), silu_f(a3y));
    }
    __syncthreads();

#pragma unroll
    for (int half = 0; half < 2; half++) {
        unsigned long long o2[16];
#pragma unroll
        for (int t = 0; t < 16; t++) o2[t] = 0ull;
        const float* wb2 = s_w2 + half * 32 + og * 8;
#pragma unroll 4
        for (int j = 0; j < 32; j++) {
            float4 a4 = *(const float4*)(s_buf + j * 260 + Eb);
            ulonglong2 u0 = *(const ulonglong2*)(wb2 + j * 64);
            ulonglong2 u1 = *(const ulonglong2*)(wb2 + j * 64 + 4);
            unsigned long long ax;
            ax = dup2(a4.x);
            ffma2(o2[0], ax, u0.x); ffma2(o2[1], ax, u0.y); ffma2(o2[2], ax, u1.x); ffma2(o2[3], ax, u1.y);
            ax = dup2(a4.y);
            ffma2(o2[4], ax, u0.x); ffma2(o2[5], ax, u0.y); ffma2(o2[6], ax, u1.x); ffma2(o2[7], ax, u1.y);
            ax = dup2(a4.z);
            ffma2(o2[8], ax, u0.x); ffma2(o2[9], ax, u0.y); ffma2(o2[10], ax, u1.x); ffma2(o2[11], ax, u1.y);
            ax = dup2(a4.w);
            ffma2(o2[12], ax, u0.x); ffma2(o2[13], ax, u0.y); ffma2(o2[14], ax, u1.x); ffma2(o2[15], ax, u1.y);
        }
#pragma unroll
        for (int e = 0; e < 4; e++) {
            int r = Eb + e;
            size_t gofs = (size_t)(e0 + r) * 64 + half * 32 + og * 8;
            float x0, x1, x2, x3, x4, x5, x6, x7;
            unpack2(o2[e * 4 + 0], x0, x1);
            unpack2(o2[e * 4 + 1], x2, x3);
            unpack2(o2[e * 4 + 2], x4, x5);
            unpack2(o2[e * 4 + 3], x6, x7);
            float4 r0 = *(const float4*)(ef + gofs);
            float4 r1 = *(const float4*)(ef + gofs + 4);
            *(float4*)(out_edge + gofs) = make_float4(x0 + r0.x, x1 + r0.y, x2 + r0.z, x3 + r0.w);
            *(float4*)(out_edge + gofs + 4) = make_float4(x4 + r1.x, x5 + r1.y, x6 + r1.z, x7 + r1.w);
        }
    }
}

// ---------------- launch ----------------
extern "C" void kernel_launch(void* const* d_in, const int* in_sizes, int n_in,
                              void* d_out, int out_size) {
    const float* bb_emb = (const float*)d_in[0];
    const float* bb_rel = (const float*)d_in[1];
    const float* ef = (const float*)d_in[2];
    const int* ei = (const int*)d_in[3];
    const void* mask = d_in[4];
    const float* Wa1 = (const float*)d_in[5];
    const float* Wa2 = (const float*)d_in[6];
    const float* Wv = (const float*)d_in[7];
    const float* Wo = (const float*)d_in[8];
    const float* W1 = (const float*)d_in[9];
    const float* W2 = (const float*)d_in[10];
    const float* We1 = (const float*)d_in[11];
    const float* We2 = (const float*)d_in[12];
    float* out_node = (float*)d_out;
    float* out_edge = out_node + (size_t)NN * 288;

    k_mask_count<<<1250, 256>>>(mask, ei);
    k_scan<<<1, 1024>>>();
    k_node_prep<<<1250, 256>>>(bb_emb, bb_rel, Wa1, Wv);
    k_logits<<<1250, 256>>>(ef, ei, Wa1, Wa2);
    k_agg<<<1250, 256>>>();
    k_node_out<<<1250, 256>>>(Wo, W1, W2, We1, out_node);
    k_edge_out<<<1250, 256>>>(ef, ei, We1, We2, out_edge);
}

// round 14
// speedup vs baseline: 1.0306x; 1.0250x over previous
#include <cuda_runtime.h>
#include <cuda_fp16.h>

#define NN 10000
#define NE 320000
#define FULLM 0xffffffffu

// ---------------- scratch ----------------
__device__ __align__(16) float g_q[NN * 64];
__device__ __align__(16) __half2 g_vh[NN * 288];   // v_nodes as half2
__device__ __align__(16) __half2 g_efh[NE * 32];   // fp16 copy of edge_features
__device__ __align__(16) float g_wexp[NE * 8];
__device__ __align__(16) float g_agg[NN * 576];
__device__ __align__(16) float g_p[NN * 64];
__device__ float g_maskf[NN];
__device__ int g_deg[NN];
__device__ int g_cur[NN];
__device__ int g_off[NN + 1];
__device__ int g_srcp[NE];

// ---------------- helpers ----------------
static __device__ __forceinline__ unsigned long long pack2(float x, float y) {
    unsigned long long r; asm("mov.b64 %0, {%1,%2};" : "=l"(r) : "f"(x), "f"(y)); return r;
}
static __device__ __forceinline__ unsigned long long dup2(float x) {
    unsigned long long r; asm("mov.b64 %0, {%1,%1};" : "=l"(r) : "f"(x)); return r;
}
static __device__ __forceinline__ void unpack2(unsigned long long v, float& x, float& y) {
    asm("mov.b64 {%0,%1}, %2;" : "=f"(x), "=f"(y) : "l"(v));
}
static __device__ __forceinline__ void ffma2(unsigned long long& d, unsigned long long a, unsigned long long b) {
    asm("fma.rn.f32x2 %0, %1, %2, %0;" : "+l"(d) : "l"(a), "l"(b));
}
static __device__ __forceinline__ float silu_f(float x) { return x / (1.f + __expf(-x)); }
static __device__ __forceinline__ unsigned long long h2f2(unsigned h) {
    float2 f = __half22float2(*(__half2*)&h);
    return pack2(f.x, f.y);
}

// ---------------- mask conv (block 0) + degree count ----------------
__global__ void k_mask_count(const void* __restrict__ p, const int* __restrict__ ei) {
    int e = blockIdx.x * 256 + threadIdx.x;
    atomicAdd(&g_deg[ei[NE + e]], 1);
    if (blockIdx.x == 0) {
        const unsigned* u = (const unsigned*)p;
        __shared__ int okf, oki;
        if (threadIdx.x == 0) { okf = 1; oki = 1; }
        __syncthreads();
        for (int i = threadIdx.x; i < 2500; i += 256) {
            unsigned v = u[i];
            if (!(v == 0u || v == 0x3F800000u)) okf = 0;
            if (!(v == 0u || v == 1u)) oki = 0;
        }
        __syncthreads();
        int t = okf ? 0 : (oki ? 1 : 2);
        for (int i = threadIdx.x; i < NN; i += 256) {
            float m;
            if (t == 0) m = ((const float*)p)[i];
            else if (t == 1) m = (float)(((const int*)p)[i] != 0);
            else m = ((const unsigned char*)p)[i] ? 1.f : 0.f;
            g_maskf[i] = m;
        }
    }
}

// ---------------- scan; resets g_deg/g_cur ----------------
__global__ void k_scan() {
    __shared__ int wsum[32];
    __shared__ int carry;
    int tid = threadIdx.x, lane = tid & 31, wid = tid >> 5;
    if (tid == 0) carry = 0;
    __syncthreads();
    for (int base = 0; base < NN; base += 1024) {
        int i = base + tid;
        int v = (i < NN) ? g_deg[i] : 0;
        int x = v;
#pragma unroll
        for (int s = 1; s < 32; s <<= 1) { int t = __shfl_up_sync(FULLM, x, s); if (lane >= s) x += t; }
        if (lane == 31) wsum[wid] = x;
        __syncthreads();
        if (wid == 0) {
            int y = wsum[lane];
#pragma unroll
            for (int s = 1; s < 32; s <<= 1) { int t = __shfl_up_sync(FULLM, y, s); if (lane >= s) y += t; }
            wsum[lane] = y;
        }
        __syncthreads();
        int prefix = carry + (wid ? wsum[wid - 1] : 0);
        if (i < NN) { g_off[i] = prefix + x - v; g_deg[i] = 0; g_cur[i] = 0; }
        __syncthreads();
        if (tid == 0) carry += wsum[31];
        __syncthreads();
    }
    if (tid == 0) g_off[NN] = NE;
}

// ---------------- node prep: q halves + v -> half2 ----------------
__global__ __launch_bounds__(256) void k_node_prep(
    const float* __restrict__ bb_emb, const float* __restrict__ bb_rel,
    const float* __restrict__ Wa1, const float* __restrict__ Wv) {
    __shared__ __align__(16) unsigned long long sWvP[35 * 32];
    __shared__ __align__(16) unsigned long long sWaP[35 * 32];
    int tid = threadIdx.x;
    for (int i = tid; i < 35 * 32; i += 256) {
        int k = i >> 5, j = i & 31;
        ((float2*)sWvP)[i] = make_float2(Wv[k * 64 + 2 * j], Wv[k * 64 + 2 * j + 1]);
        ((float2*)sWaP)[i] = make_float2(Wa1[k * 32 + j], Wa1[(k + 35) * 32 + j]);
    }
    __syncthreads();
    int lane = tid & 31;
    int n = blockIdx.x * 8 + (tid >> 5);
    float mk = g_maskf[n];

    float r0 = bb_emb[n * 288 + lane];
    unsigned long long accq = 0ull;
#pragma unroll
    for (int k = 0; k < 32; k++)
        ffma2(accq, dup2(__shfl_sync(FULLM, r0, k)), sWaP[k * 32 + lane]);
    ffma2(accq, dup2(mk), sWaP[34 * 32 + lane]);
    float qs, qd; unpack2(accq, qs, qd);
    g_q[n * 64 + lane] = qs;
    g_q[n * 64 + 32 + lane] = qd;

#pragma unroll
    for (int c = 0; c < 9; c++) {
        float f = bb_emb[n * 288 + c * 32 + lane];
        unsigned long long acc = 0ull;
        if (c == 0) {
            ffma2(acc, dup2(mk), sWvP[34 * 32 + lane]);
        } else if (c <= 3) {
#pragma unroll
            for (int b = 0; b < 3; b++)
                ffma2(acc, dup2(bb_rel[n * 9 + b * 3 + (c - 1)]), sWvP[(32 + b) * 32 + lane]);
        }
#pragma unroll
        for (int k = 0; k < 32; k++)
            ffma2(acc, dup2(__shfl_sync(FULLM, f, k)), sWvP[k * 32 + lane]);
        float a0, a1; unpack2(acc, a0, a1);
        g_vh[n * 288 + c * 32 + lane] = __floats2half2_rn(a0, a1);
    }
}

// ---------------- edge logits: register-tiled GEMM; also emits fp16 ef copy ----------------
__global__ __launch_bounds__(256, 3) void k_logits(
    const float* __restrict__ ef, const int* __restrict__ ei,
    const float* __restrict__ Wa1, const float* __restrict__ Wa2) {
    __shared__ __align__(16) float s_buf[9216];
    __shared__ __align__(16) float s_w[2048];
    __shared__ __align__(16) float s_w2r[4 * 264];
    __shared__ int s_si[256], s_di[256];
    int tid = threadIdx.x;
    int e0 = blockIdx.x * 256;
    for (int i = tid; i < 2048; i += 256) s_w[i] = Wa1[2240 + i];
    for (int i = tid; i < 1024; i += 256) s_w2r[(i >> 8) * 264 + (i & 255)] = Wa2[i & 255];
    s_si[tid] = ei[e0 + tid]; s_di[tid] = ei[NE + e0 + tid];
    __syncthreads();

    float4* qv4 = (float4*)s_buf;
    for (int i = tid; i < 2048; i += 256) {
        int r = i >> 3, slot = i & 7;
        float4 a = ((const float4*)(g_q + s_si[r] * 64))[slot];
        float4 b = ((const float4*)(g_q + s_di[r] * 64 + 32))[slot];
        qv4[r * 9 + slot] = make_float4(a.x + b.x, a.y + b.y, a.z + b.z, a.w + b.w);
    }
    __syncthreads();

    int lane = tid & 31, w = tid >> 5;
    int eg = lane & 7, og = lane >> 3;
    int Eb = w * 32 + eg * 4;
    int gb = Eb >> 2;
    unsigned long long acc[16];
#pragma unroll
    for (int e = 0; e < 4; e++) {
        float4 fa = qv4[(Eb + e) * 9 + og * 2];
        float4 fb = qv4[(Eb + e) * 9 + og * 2 + 1];
        acc[e * 4 + 0] = pack2(fa.x, fa.y);
        acc[e * 4 + 1] = pack2(fa.z, fa.w);
        acc[e * 4 + 2] = pack2(fb.x, fb.y);
        acc[e * 4 + 3] = pack2(fb.z, fb.w);
    }

#pragma unroll
    for (int ph = 0; ph < 2; ph++) {
        __syncthreads();
        for (int i = tid; i < 2048; i += 256) {
            int r = i >> 3, c4 = i & 7;
            float4 v = *(const float4*)(ef + (size_t)(e0 + r) * 64 + ph * 32 + c4 * 4);
            // fp16 copy for k_edge_out
            __half2 h01 = __floats2half2_rn(v.x, v.y);
            __half2 h23 = __floats2half2_rn(v.z, v.w);
            *(uint2*)(g_efh + (size_t)(e0 + r) * 32 + ph * 16 + c4 * 2) =
                make_uint2(*(unsigned*)&h01, *(unsigned*)&h23);
            int g = r >> 2, rl = r & 3;
            int gs = (g & 56) | ((g ^ c4) & 7);
            float* dp = s_buf + gs * 4 + rl;
            dp[(c4 * 4 + 0) * 260] = v.x;
            dp[(c4 * 4 + 1) * 260] = v.y;
            dp[(c4 * 4 + 2) * 260] = v.z;
            dp[(c4 * 4 + 3) * 260] = v.w;
        }
        __syncthreads();
        const float* wbase = s_w + ph * 1024 + og * 8;
#pragma unroll 4
        for (int k = 0; k < 32; k++) {
            int gs = (gb & 56) | ((gb ^ (k >> 2)) & 7);
            float4 a4 = *(const float4*)(s_buf + k * 260 + gs * 4);
            ulonglong2 u0 = *(const ulonglong2*)(wbase + k * 32);
            ulonglong2 u1 = *(const ulonglong2*)(wbase + k * 32 + 4);
            unsigned long long ax;
            ax = dup2(a4.x);
            ffma2(acc[0], ax, u0.x); ffma2(acc[1], ax, u0.y); ffma2(acc[2], ax, u1.x); ffma2(acc[3], ax, u1.y);
            ax = dup2(a4.y);
            ffma2(acc[4], ax, u0.x); ffma2(acc[5], ax, u0.y); ffma2(acc[6], ax, u1.x); ffma2(acc[7], ax, u1.y);
            ax = dup2(a4.z);
            ffma2(acc[8], ax, u0.x); ffma2(acc[9], ax, u0.y); ffma2(acc[10], ax, u1.x); ffma2(acc[11], ax, u1.y);
            ax = dup2(a4.w);
            ffma2(acc[12], ax, u0.x); ffma2(acc[13], ax, u0.y); ffma2(acc[14], ax, u1.x); ffma2(acc[15], ax, u1.y);
        }
    }

    const float* w2b = s_w2r + og * 264;
#pragma unroll
    for (int e = 0; e < 4; e++) {
        int r = Eb + e;
        float pl[8] = {0, 0, 0, 0, 0, 0, 0, 0};
#pragma unroll
        for (int p = 0; p < 4; p++) {
            float x0, x1; unpack2(acc[e * 4 + p], x0, x1);
            float s0 = silu_f(x0), s1 = silu_f(x1);
            const float4* wr = (const float4*)(w2b + (og * 8 + 2 * p) * 8);
            float4 wa = wr[0], wb = wr[1], wc = wr[2], wd = wr[3];
            pl[0] += s0 * wa.x + s1 * wc.x; pl[1] += s0 * wa.y + s1 * wc.y;
            pl[2] += s0 * wa.z + s1 * wc.z; pl[3] += s0 * wa.w + s1 * wc.w;
            pl[4] += s0 * wb.x + s1 * wd.x; pl[5] += s0 * wb.y + s1 * wd.y;
            pl[6] += s0 * wb.z + s1 * wd.z; pl[7] += s0 * wb.w + s1 * wd.w;
        }
#pragma unroll
        for (int h = 0; h < 8; h++) {
            pl[h] += __shfl_xor_sync(FULLM, pl[h], 8);
            pl[h] += __shfl_xor_sync(FULLM, pl[h], 16);
        }
        if (og == 0) {
            int d = s_di[r];
            int pos = g_off[d] + atomicAdd(&g_cur[d], 1);
            g_srcp[pos] = s_si[r];
            float4* lo = (float4*)(g_wexp + (size_t)pos * 8);
            lo[0] = make_float4(__expf(pl[0]), __expf(pl[1]), __expf(pl[2]), __expf(pl[3]));
            lo[1] = make_float4(__expf(pl[4]), __expf(pl[5]), __expf(pl[6]), __expf(pl[7]));
        }
    }
}

// ---------------- single-pass softmax aggregation over fp16 v ----------------
__global__ __launch_bounds__(256) void k_agg() {
    int lane = threadIdx.x & 31, wid = threadIdx.x >> 5;
    int n = blockIdx.x * 8 + wid;
    int st = g_off[n], en = g_off[n + 1];
    int hl = lane & 7;
    float z = 0.f;
    unsigned long long A[4] = {0, 0, 0, 0}, B[4] = {0, 0, 0, 0}, C[4] = {0, 0, 0, 0};
    if (st < en) {
        int s_nxt = __ldg(&g_srcp[st]);
        float w_nxt = __ldg(&g_wexp[(size_t)st * 8 + hl]);
        for (int i = st; i < en; i++) {
            int s = s_nxt;
            float w = w_nxt;
            int ip = (i + 1 < en) ? i + 1 : i;
            s_nxt = __ldg(&g_srcp[ip]);
            w_nxt = __ldg(&g_wexp[(size_t)ip * 8 + hl]);
            z += w;
            unsigned long long w2 = dup2(w);
            const uint4* vb = (const uint4*)(g_vh + (size_t)s * 288);
            uint4 u;
            u = vb[lane];
            ffma2(A[0], w2, h2f2(u.x)); ffma2(A[1], w2, h2f2(u.y));
            ffma2(A[2], w2, h2f2(u.z)); ffma2(A[3], w2, h2f2(u.w));
            u = vb[32 + lane];
            ffma2(B[0], w2, h2f2(u.x)); ffma2(B[1], w2, h2f2(u.y));
            ffma2(B[2], w2, h2f2(u.z)); ffma2(B[3], w2, h2f2(u.w));
            if (lane < 8) {
                u = vb[64 + lane];
                ffma2(C[0], w2, h2f2(u.x)); ffma2(C[1], w2, h2f2(u.y));
                ffma2(C[2], w2, h2f2(u.z)); ffma2(C[3], w2, h2f2(u.w));
            }
        }
    }
    float rz = 1.f / (z + 1e-9f);
    float4* ag4 = (float4*)(g_agg + n * 576);
    float x0, x1, x2, x3;
    unpack2(A[0], x0, x1); unpack2(A[1], x2, x3);
    ag4[2 * lane] = make_float4(x0 * rz, x1 * rz, x2 * rz, x3 * rz);
    unpack2(A[2], x0, x1); unpack2(A[3], x2, x3);
    ag4[2 * lane + 1] = make_float4(x0 * rz, x1 * rz, x2 * rz, x3 * rz);
    unpack2(B[0], x0, x1); unpack2(B[1], x2, x3);
    ag4[2 * lane + 64] = make_float4(x0 * rz, x1 * rz, x2 * rz, x3 * rz);
    unpack2(B[2], x0, x1); unpack2(B[3], x2, x3);
    ag4[2 * lane + 65] = make_float4(x0 * rz, x1 * rz, x2 * rz, x3 * rz);
    if (lane < 8) {
        unpack2(C[0], x0, x1); unpack2(C[1], x2, x3);
        ag4[2 * lane + 128] = make_float4(x0 * rz, x1 * rz, x2 * rz, x3 * rz);
        unpack2(C[2], x0, x1); unpack2(C[3], x2, x3);
        ag4[2 * lane + 129] = make_float4(x0 * rz, x1 * rz, x2 * rz, x3 * rz);
    }
}

// ---------------- node output MLP + p precompute ----------------
__global__ __launch_bounds__(256) void k_node_out(
    const float* __restrict__ Wo, const float* __restrict__ W1,
    const float* __restrict__ W2, const float* __restrict__ We1,
    float* __restrict__ out_node) {
    __shared__ __align__(16) float2 sWoP[32 * 32];
    __shared__ float sW1[1024], sW2[1024], sWe[2048];
    __shared__ __align__(16) float sAgg[8 * 576];
    int tid = threadIdx.x;
    for (int i = tid; i < 1024; i += 256) {
        int jp = i >> 5, l = i & 31;
        sWoP[i] = make_float2(Wo[(2 * jp) * 32 + l], Wo[(2 * jp + 1) * 32 + l]);
        sW1[i] = W1[i]; sW2[i] = W2[i];
    }
    for (int i = tid; i < 2048; i += 256) sWe[i] = We1[i];
    {
        const float4* src = (const float4*)(g_agg + (size_t)blockIdx.x * 8 * 576);
        float4* dst = (float4*)sAgg;
        for (int i = tid; i < 8 * 144; i += 256) dst[i] = src[i];
    }
    __syncthreads();
    int lane = tid & 31, wid = tid >> 5;
    int n = blockIdx.x * 8 + wid;
    const float* sa = sAgg + wid * 576;

    float ao[9];
#pragma unroll
    for (int c = 0; c < 9; c++) {
        unsigned long long acc2 = 0ull;
        const unsigned long long* sav = (const unsigned long long*)(sa + c * 64);
#pragma unroll
        for (int jp = 0; jp < 32; jp++)
            ffma2(acc2, sav[jp], *(const unsigned long long*)&sWoP[jp * 32 + lane]);
        float x0, x1; unpack2(acc2, x0, x1);
        ao[c] = x0 + x1;
    }
    float hr[9];
#pragma unroll
    for (int c = 0; c < 9; c++) {
        float acc = 0.f;
#pragma unroll
        for (int o = 0; o < 32; o++) acc += __shfl_sync(FULLM, ao[c], o) * sW1[o * 32 + lane];
        hr[c] = acc;
    }
    float gate = silu_f(hr[0]);
    float nn0 = 0.f;
#pragma unroll
    for (int c = 0; c < 9; c++) {
        float t = hr[c] * gate;
        float acc = ao[c];
#pragma unroll
        for (int o = 0; o < 32; o++) acc += __shfl_sync(FULLM, t, o) * sW2[o * 32 + lane];
        out_node[n * 288 + c * 32 + lane] = acc;
        if (c == 0) nn0 = acc;
    }
    float ps = 0.f, pd = 0.f;
#pragma unroll
    for (int k = 0; k < 32; k++) {
        float u = __shfl_sync(FULLM, nn0, k);
        ps += u * sWe[k * 32 + lane];
        pd += u * sWe[(32 + k) * 32 + lane];
    }
    g_p[n * 64 + lane] = ps;
    g_p[n * 64 + 32 + lane] = pd;
}

// ---------------- edge output MLP: fp16 ef stream, register-tiled ----------------
__global__ __launch_bounds__(256, 3) void k_edge_out(
    const int* __restrict__ ei,
    const float* __restrict__ We1, const float* __restrict__ We2,
    float* __restrict__ out_edge) {
    __shared__ __align__(16) float s_buf[9216];
    __shared__ __align__(16) float s_w1[2048];
    __shared__ __align__(16) float s_w2[2048];
    __shared__ int s_si[256], s_di[256];
    int tid = threadIdx.x;
    int e0 = blockIdx.x * 256;
    for (int i = tid; i < 2048; i += 256) { s_w1[i] = We1[2048 + i]; s_w2[i] = We2[i]; }
    s_si[tid] = ei[e0 + tid]; s_di[tid] = ei[NE + e0 + tid];
    __syncthreads();

    float4* qv4 = (float4*)s_buf;
    for (int i = tid; i < 2048; i += 256) {
        int r = i >> 3, slot = i & 7;
        float4 a = ((const float4*)(g_p + s_si[r] * 64))[slot];
        float4 b = ((const float4*)(g_p + s_di[r] * 64 + 32))[slot];
        qv4[r * 9 + slot] = make_float4(a.x + b.x, a.y + b.y, a.z + b.z, a.w + b.w);
    }
    __syncthreads();

    int lane = tid & 31, w = tid >> 5;
    int eg = lane & 7, og = lane >> 3;
    int Eb = w * 32 + eg * 4;
    int gb = Eb >> 2;
    unsigned long long acc[16];
#pragma unroll
    for (int e = 0; e < 4; e++) {
        float4 fa = qv4[(Eb + e) * 9 + og * 2];
        float4 fb = qv4[(Eb + e) * 9 + og * 2 + 1];
        acc[e * 4 + 0] = pack2(fa.x, fa.y);
        acc[e * 4 + 1] = pack2(fa.z, fa.w);
        acc[e * 4 + 2] = pack2(fb.x, fb.y);
        acc[e * 4 + 3] = pack2(fb.z, fb.w);
    }

#pragma unroll
    for (int ph = 0; ph < 2; ph++) {
        __syncthreads();
        for (int i = tid; i < 2048; i += 256) {
            int r = i >> 3, c4 = i & 7;
            uint2 u = *(const uint2*)(g_efh + (size_t)(e0 + r) * 32 + ph * 16 + c4 * 2);
            float2 f01 = __half22float2(*(__half2*)&u.x);
            float2 f23 = __half22float2(*(__half2*)&u.y);
            int g = r >> 2, rl = r & 3;
            int gs = (g & 56) | ((g ^ c4) & 7);
            float* dp = s_buf + gs * 4 + rl;
            dp[(c4 * 4 + 0) * 260] = f01.x;
            dp[(c4 * 4 + 1) * 260] = f01.y;
            dp[(c4 * 4 + 2) * 260] = f23.x;
            dp[(c4 * 4 + 3) * 260] = f23.y;
        }
        __syncthreads();
        const float* wbase = s_w1 + ph * 1024 + og * 8;
#pragma unroll 4
        for (int k = 0; k < 32; k++) {
            int gs = (gb & 56) | ((gb ^ (k >> 2)) & 7);
            float4 a4 = *(const float4*)(s_buf + k * 260 + gs * 4);
            ulonglong2 u0 = *(const ulonglong2*)(wbase + k * 32);
            ulonglong2 u1 = *(const ulonglong2*)(wbase + k * 32 + 4);
            unsigned long long ax;
            ax = dup2(a4.x);
            ffma2(acc[0], ax, u0.x); ffma2(acc[1], ax, u0.y); ffma2(acc[2], ax, u1.x); ffma2(acc[3], ax, u1.y);
            ax = dup2(a4.y);
            ffma2(acc[4], ax, u0.x); ffma2(acc[5], ax, u0.y); ffma2(acc[6], ax, u1.x); ffma2(acc[7], ax, u1.y);
            ax = dup2(a4.z);
            ffma2(acc[8], ax, u0.x); ffma2(acc[9], ax, u0.y); ffma2(acc[10], ax, u1.x); ffma2(acc[11], ax, u1.y);
            ax = dup2(a4.w);
            ffma2(acc[12], ax, u0.x); ffma2(acc[13], ax, u0.y); ffma2(acc[14], ax, u1.x); ffma2(acc[15], ax, u1.y);
        }
    }

    __syncthreads();
#pragma unroll
    for (int p = 0; p < 4; p++) {
        float a0x, a0y, a1x, a1y, a2x, a2y, a3x, a3y;
        unpack2(acc[0 * 4 + p], a0x, a0y);
        unpack2(acc[1 * 4 + p], a1x, a1y);
        unpack2(acc[2 * 4 + p], a2x, a2y);
        unpack2(acc[3 * 4 + p], a3x, a3y);
        int j = og * 8 + 2 * p;
        *(float4*)(s_buf + j * 260 + Eb) =
            make_float4(silu_f(a0x), silu_f(a1x), silu_f(a2x), silu_f(a3x));
        *(float4*)(s_buf + (j + 1) * 260 + Eb) =
            make_float4(silu_f(a0y), silu_f(a1y), silu_f(a2y), silu_f(a3y));
    }
    __syncthreads();

#pragma unroll
    for (int half = 0; half < 2; half++) {
        unsigned long long o2[16];
#pragma unroll
        for (int t = 0; t < 16; t++) o2[t] = 0ull;
        const float* wb2 = s_w2 + half * 32 + og * 8;
#pragma unroll 4
        for (int j = 0; j < 32; j++) {
            float4 a4 = *(const float4*)(s_buf + j * 260 + Eb);
            ulonglong2 u0 = *(const ulonglong2*)(wb2 + j * 64);
            ulonglong2 u1 = *(const ulonglong2*)(wb2 + j * 64 + 4);
            unsigned long long ax;
            ax = dup2(a4.x);
            ffma2(o2[0], ax, u0.x); ffma2(o2[1], ax, u0.y); ffma2(o2[2], ax, u1.x); ffma2(o2[3], ax, u1.y);
            ax = dup2(a4.y);
            ffma2(o2[4], ax, u0.x); ffma2(o2[5], ax, u0.y); ffma2(o2[6], ax, u1.x); ffma2(o2[7], ax, u1.y);
            ax = dup2(a4.z);
            ffma2(o2[8], ax, u0.x); ffma2(o2[9], ax, u0.y); ffma2(o2[10], ax, u1.x); ffma2(o2[11], ax, u1.y);
            ax = dup2(a4.w);
            ffma2(o2[12], ax, u0.x); ffma2(o2[13], ax, u0.y); ffma2(o2[14], ax, u1.x); ffma2(o2[15], ax, u1.y);
        }
#pragma unroll
        for (int e = 0; e < 4; e++) {
            int r = Eb + e;
            size_t gofs = (size_t)(e0 + r) * 64 + half * 32 + og * 8;
            float x0, x1, x2, x3, x4, x5, x6, x7;
            unpack2(o2[e * 4 + 0], x0, x1);
            unpack2(o2[e * 4 + 1], x2, x3);
            unpack2(o2[e * 4 + 2], x4, x5);
            unpack2(o2[e * 4 + 3], x6, x7);
            uint2 ur0 = *(const uint2*)(g_efh + gofs / 2);
            uint2 ur1 = *(const uint2*)(g_efh + gofs / 2 + 2);
            float2 ra = __half22float2(*(__half2*)&ur0.x);
            float2 rb = __half22float2(*(__half2*)&ur0.y);
            float2 rc = __half22float2(*(__half2*)&ur1.x);
            float2 rd = __half22float2(*(__half2*)&ur1.y);
            *(float4*)(out_edge + gofs) = make_float4(x0 + ra.x, x1 + ra.y, x2 + rb.x, x3 + rb.y);
            *(float4*)(out_edge + gofs + 4) = make_float4(x4 + rc.x, x5 + rc.y, x6 + rd.x, x7 + rd.y);
        }
    }
}

// ---------------- launch ----------------
extern "C" void kernel_launch(void* const* d_in, const int* in_sizes, int n_in,
                              void* d_out, int out_size) {
    const float* bb_emb = (const float*)d_in[0];
    const float* bb_rel = (const float*)d_in[1];
    const float* ef = (const float*)d_in[2];
    const int* ei = (const int*)d_in[3];
    const void* mask = d_in[4];
    const float* Wa1 = (const float*)d_in[5];
    const float* Wa2 = (const float*)d_in[6];
    const float* Wv = (const float*)d_in[7];
    const float* Wo = (const float*)d_in[8];
    const float* W1 = (const float*)d_in[9];
    const float* W2 = (const float*)d_in[10];
    const float* We1 = (const float*)d_in[11];
    const float* We2 = (const float*)d_in[12];
    float* out_node = (float*)d_out;
    float* out_edge = out_node + (size_t)NN * 288;

    k_mask_count<<<1250, 256>>>(mask, ei);
    k_scan<<<1, 1024>>>();
    k_node_prep<<<1250, 256>>>(bb_emb, bb_rel, Wa1, Wv);
    k_logits<<<1250, 256>>>(ef, ei, Wa1, Wa2);
    k_agg<<<1250, 256>>>();
    k_node_out<<<1250, 256>>>(Wo, W1, W2, We1, out_node);
    k_edge_out<<<1250, 256>>>(ei, We1, We2, out_edge);
}